// round 14
// baseline (speedup 1.0000x reference)
#include <cuda_runtime.h>
#include <cuda_bf16.h>
#include <cstdint>

#define N_NODES 100000
#define N_EDGES 1600000
#define D 128
#define K2 256

#define SCAN_NBLK ((N_NODES + 4095) / 4096)   // 25

// ---------------- scratch (device globals; no allocation allowed) ----------
__device__ int   g_deg[N_NODES];
__device__ int   g_off[N_NODES + 1];
__device__ int   g_cursor[N_NODES];
__device__ int   g_srcs[N_EDGES];
__device__ int   g_blksum[32];
__device__ __nv_bfloat16 g_hhi[(size_t)N_NODES * D];    // h bf16 hi
__device__ __nv_bfloat16 g_hlo[(size_t)N_NODES * D];    // h bf16 lo
__device__ __nv_bfloat16 g_ahnhi[(size_t)N_NODES * D];  // ahn bf16 hi
__device__ __nv_bfloat16 g_ahnlo[(size_t)N_NODES * D];  // ahn bf16 lo
__device__ __nv_bfloat16 g_Whi[128 * 256];              // W bf16 hi
__device__ __nv_bfloat16 g_Wlo[128 * 256];              // W bf16 lo

__device__ __forceinline__ uint32_t pack_hi2(float a, float b, uint32_t& lo) {
    __nv_bfloat162 h2 = __floats2bfloat162_rn(a, b);
    float2 f = __bfloat1622float2(h2);
    __nv_bfloat162 l2 = __floats2bfloat162_rn(a - f.x, b - f.y);
    lo = *(uint32_t*)&l2;
    return *(uint32_t*)&h2;
}

// ---------------- init: zero degrees + convert W to bf16 hi/lo ---------------
__global__ void k_init(const float* __restrict__ W) {
    int i = blockIdx.x * blockDim.x + threadIdx.x;
    if (i < N_NODES) g_deg[i] = 0;
    if (i < 128 * 256) {
        float v = W[i];
        __nv_bfloat16 hi = __float2bfloat16(v);
        g_Whi[i] = hi;
        g_Wlo[i] = __float2bfloat16(v - __bfloat162float(hi));
    }
}

// ---- count degrees AND convert h -> bf16 hi/lo (disjoint thread ranges) -----
__global__ void k_count_convh(const int* __restrict__ dst,
                              const float* __restrict__ h) {
    int i = blockIdx.x * blockDim.x + threadIdx.x;   // 0 .. 3.2M-1
    if (i < N_EDGES) atomicAdd(&g_deg[dst[i]], 1);
    if (i < N_NODES * 32) {
        float4 v = ((const float4*)h)[i];
        uint32_t lo0, lo1;
        uint32_t hi0 = pack_hi2(v.x, v.y, lo0);
        uint32_t hi1 = pack_hi2(v.z, v.w, lo1);
        ((uint2*)g_hhi)[i] = make_uint2(hi0, hi1);
        ((uint2*)g_hlo)[i] = make_uint2(lo0, lo1);
    }
}

// ---- scan pass 1: per-block exclusive scan + block sums ---------------------
__global__ void k_scan1() {
    __shared__ int wsum[32];
    const int b = blockIdx.x, t = threadIdx.x;
    const int lane = t & 31, wid = t >> 5;
    const int base = b * 4096 + t * 4;

    int v0 = 0, v1 = 0, v2 = 0, v3 = 0;
    if (base + 3 < N_NODES) {
        int4 vv = *(const int4*)&g_deg[base];
        v0 = vv.x; v1 = vv.y; v2 = vv.z; v3 = vv.w;
    } else {
        if (base + 0 < N_NODES) v0 = g_deg[base + 0];
        if (base + 1 < N_NODES) v1 = g_deg[base + 1];
        if (base + 2 < N_NODES) v2 = g_deg[base + 2];
        if (base + 3 < N_NODES) v3 = g_deg[base + 3];
    }
    int tsum = v0 + v1 + v2 + v3;

    int x = tsum;
#pragma unroll
    for (int o = 1; o < 32; o <<= 1) {
        int y = __shfl_up_sync(0xffffffffu, x, o);
        if (lane >= o) x += y;
    }
    if (lane == 31) wsum[wid] = x;
    __syncthreads();
    if (wid == 0) {
        int w = wsum[lane];
        int xx = w;
#pragma unroll
        for (int o = 1; o < 32; o <<= 1) {
            int y = __shfl_up_sync(0xffffffffu, xx, o);
            if (lane >= o) xx += y;
        }
        wsum[lane] = xx - w;
        if (lane == 31) g_blksum[b] = xx;
    }
    __syncthreads();

    int prefix = wsum[wid] + (x - tsum);
    if (base + 3 < N_NODES) {
        *(int4*)&g_off[base] = make_int4(prefix, prefix + v0,
                                         prefix + v0 + v1, prefix + v0 + v1 + v2);
    } else {
        if (base + 0 < N_NODES) g_off[base + 0] = prefix;
        if (base + 1 < N_NODES) g_off[base + 1] = prefix + v0;
        if (base + 2 < N_NODES) g_off[base + 2] = prefix + v0 + v1;
        if (base + 3 < N_NODES) g_off[base + 3] = prefix + v0 + v1 + v2;
    }
}

// ---- scan pass 2: every block redundantly scans block sums, applies ---------
__global__ void k_scan23() {
    __shared__ int s_off;
    const int b = blockIdx.x, t = threadIdx.x;

    if (t < 32) {
        int v = (t < SCAN_NBLK) ? g_blksum[t] : 0;
        int x = v;
#pragma unroll
        for (int o = 1; o < 32; o <<= 1) {
            int y = __shfl_up_sync(0xffffffffu, x, o);
            if (t >= o) x += y;
        }
        if (t == b) s_off = x - v;
    }
    __syncthreads();
    const int off = s_off;

    const int base = b * 4096 + t * 4;
    if (base + 3 < N_NODES) {
        int4 vv = *(const int4*)&g_off[base];
        vv.x += off; vv.y += off; vv.z += off; vv.w += off;
        *(int4*)&g_off[base] = vv;
        *(int4*)&g_cursor[base] = vv;
    } else {
#pragma unroll
        for (int j = 0; j < 4; j++) {
            int idx = base + j;
            if (idx < N_NODES) {
                int val = g_off[idx] + off;
                g_off[idx] = val;
                g_cursor[idx] = val;
            }
        }
    }
    if (b == 0 && t == 0) g_off[N_NODES] = N_EDGES;
}

__global__ void k_scatter(const int* __restrict__ src, const int* __restrict__ dst) {
    int e = blockIdx.x * blockDim.x + threadIdx.x;
    if (e < N_EDGES) {
        int p = atomicAdd(&g_cursor[dst[e]], 1);
        g_srcs[p] = src[e];
    }
}

// ---------------- aggregation: fp32 gather, write bf16 hi/lo -----------------
__global__ void k_aggregate(const float* __restrict__ h) {
    int warp = (blockIdx.x * blockDim.x + threadIdx.x) >> 5;
    int lane = threadIdx.x & 31;
    if (warp >= N_NODES) return;
    int beg = g_off[warp];
    int end = g_off[warp + 1];
    const float4* h4 = (const float4*)h;
    float4 acc0 = make_float4(0.f, 0.f, 0.f, 0.f);
    float4 acc1 = make_float4(0.f, 0.f, 0.f, 0.f);
    int e = beg;
    for (; e + 3 < end; e += 4) {
        int s0 = __ldg(&g_srcs[e]);
        int s1 = __ldg(&g_srcs[e + 1]);
        int s2 = __ldg(&g_srcs[e + 2]);
        int s3 = __ldg(&g_srcs[e + 3]);
        float4 v0 = __ldg(&h4[(size_t)s0 * 32 + lane]);
        float4 v1 = __ldg(&h4[(size_t)s1 * 32 + lane]);
        float4 v2 = __ldg(&h4[(size_t)s2 * 32 + lane]);
        float4 v3 = __ldg(&h4[(size_t)s3 * 32 + lane]);
        acc0.x += v0.x; acc0.y += v0.y; acc0.z += v0.z; acc0.w += v0.w;
        acc1.x += v1.x; acc1.y += v1.y; acc1.z += v1.z; acc1.w += v1.w;
        acc0.x += v2.x; acc0.y += v2.y; acc0.z += v2.z; acc0.w += v2.w;
        acc1.x += v3.x; acc1.y += v3.y; acc1.z += v3.z; acc1.w += v3.w;
    }
    for (; e < end; e++) {
        int s0 = __ldg(&g_srcs[e]);
        float4 v0 = __ldg(&h4[(size_t)s0 * 32 + lane]);
        acc0.x += v0.x; acc0.y += v0.y; acc0.z += v0.z; acc0.w += v0.w;
    }
    acc0.x += acc1.x; acc0.y += acc1.y; acc0.z += acc1.z; acc0.w += acc1.w;
    float norm = (end > beg) ? 1.0f / (float)(end - beg) : 0.0f;
    acc0.x *= norm; acc0.y *= norm; acc0.z *= norm; acc0.w *= norm;

    uint32_t lo0, lo1;
    uint32_t hi0 = pack_hi2(acc0.x, acc0.y, lo0);
    uint32_t hi1 = pack_hi2(acc0.z, acc0.w, lo1);
    ((uint2*)g_ahnhi)[(size_t)warp * 32 + lane] = make_uint2(hi0, hi1);
    ((uint2*)g_ahnlo)[(size_t)warp * 32 + lane] = make_uint2(lo0, lo1);
}

// =============== tensor-core GEMM + LN + ReLU (mma.sync bf16 hi/lo) ==========
// CTA: 128x128, 512 threads, 2 CTAs/SM. K=256 in 4 chunks; all operands
// pre-converted to bf16 hi/lo in global; staged with cp.async (zero cvt work).
#define ASTR 72
#define ABYTES (128 * ASTR * 2)
#define OFF_WHI 0
#define OFF_WLO (ABYTES)
#define OFF_AHI (2 * ABYTES)
#define OFF_ALO (3 * ABYTES)
#define TC_SMEM (4 * ABYTES)          // 73728 -> 2 CTAs/SM
#define OSTR 132

__device__ __forceinline__ uint32_t smem_u32(const void* p) {
    uint32_t a;
    asm("{ .reg .u64 t; cvta.to.shared.u64 t, %1; cvt.u32.u64 %0, t; }"
        : "=r"(a) : "l"(p));
    return a;
}

__device__ __forceinline__ void cpasync16(uint32_t smaddr, const void* gptr) {
    asm volatile("cp.async.cg.shared.global [%0], [%1], 16;"
                 :: "r"(smaddr), "l"(gptr));
}

__device__ __forceinline__ void ldm4(uint32_t* r, uint32_t addr) {
    asm volatile("ldmatrix.sync.aligned.m8n8.x4.shared.b16 {%0,%1,%2,%3}, [%4];"
        : "=r"(r[0]), "=r"(r[1]), "=r"(r[2]), "=r"(r[3]) : "r"(addr));
}

__device__ __forceinline__ void mma_bf16(float* c, const uint32_t* a,
                                         uint32_t b0, uint32_t b1) {
    asm volatile("mma.sync.aligned.m16n8k16.row.col.f32.bf16.bf16.f32 "
        "{%0,%1,%2,%3}, {%4,%5,%6,%7}, {%8,%9}, {%0,%1,%2,%3};"
        : "+f"(c[0]), "+f"(c[1]), "+f"(c[2]), "+f"(c[3])
        : "r"(a[0]), "r"(a[1]), "r"(a[2]), "r"(a[3]), "r"(b0), "r"(b1));
}

__global__ void __launch_bounds__(512, 2)
k_gemm_tc(const float* __restrict__ bias,
          const float* __restrict__ gamma,
          const float* __restrict__ beta,
          float* __restrict__ out)
{
    extern __shared__ char sm[];
    const uint32_t smb = smem_u32(sm);

    const int tid = threadIdx.x;
    const int wid = tid >> 5;
    const int lane = tid & 31;
    const int wm = wid & 3;
    const int wn = wid >> 2;
    const int row0 = blockIdx.x * 128;

    const int sr = tid >> 2;       // staging row 0..127
    const int sq = tid & 3;        // staging quarter (32 bf16 = 2x16B)

    float c[2][4][4];
#pragma unroll
    for (int i = 0; i < 2; i++)
#pragma unroll
        for (int j = 0; j < 4; j++)
#pragma unroll
            for (int k = 0; k < 4; k++) c[i][j][k] = 0.f;

    const int lrow = lane & 15;
    const int lhalfB = (lane >> 4) * 16;
    const uint32_t aRowB = (uint32_t)(wm * 32 + lrow) * (ASTR * 2);
    const uint32_t wRowB = (uint32_t)(wn * 32 + lrow) * (ASTR * 2);

    int growA = row0 + sr;
    if (growA >= N_NODES) growA = N_NODES - 1;
    const size_t aRow = (size_t)growA * 128;     // bf16 elements per row
    const int wRow = sr * 256;                   // W row (bf16 elements)
    const uint32_t stOff = smb + (uint32_t)((sr * ASTR + sq * 16) * 2);

#pragma unroll 1
    for (int kb = 0; kb < 4; kb++) {
        if (kb > 0) __syncthreads();   // all reads of prev chunk done

        // ---- stage chunk kb via cp.async (raw bf16 bytes) -------------------
        const __nv_bfloat16* ahis = (kb < 2) ? g_hhi : g_ahnhi;
        const __nv_bfloat16* alos = (kb < 2) ? g_hlo : g_ahnlo;
        const int acol = (kb & 1) * 64 + sq * 16;
        const int wcol = kb * 64 + sq * 16;
#pragma unroll
        for (int cch = 0; cch < 2; cch++) {
            const int eo = cch * 8;          // 8 bf16 = 16 B
            cpasync16(stOff + OFF_AHI + eo * 2, ahis + aRow + acol + eo);
            cpasync16(stOff + OFF_ALO + eo * 2, alos + aRow + acol + eo);
            cpasync16(stOff + OFF_WHI + eo * 2, g_Whi + wRow + wcol + eo);
            cpasync16(stOff + OFF_WLO + eo * 2, g_Wlo + wRow + wcol + eo);
        }
        asm volatile("cp.async.commit_group;");
        asm volatile("cp.async.wait_group 0;");
        __syncthreads();

        // ---- mma over this chunk: 4 k-steps of 16 ---------------------------
#pragma unroll
        for (int ks = 0; ks < 4; ks++) {
            const uint32_t cb = (uint32_t)(ks * 32 + lhalfB);
            uint32_t ah[2][4], al[2][4], wh[2][4], wl[2][4];
#pragma unroll
            for (int mf = 0; mf < 2; mf++) {
                uint32_t ro = aRowB + mf * 16 * (ASTR * 2) + cb;
                ldm4(ah[mf], smb + OFF_AHI + ro);
                ldm4(al[mf], smb + OFF_ALO + ro);
            }
#pragma unroll
            for (int nx = 0; nx < 2; nx++) {
                uint32_t ro = wRowB + nx * 16 * (ASTR * 2) + cb;
                ldm4(wh[nx], smb + OFF_WHI + ro);
                ldm4(wl[nx], smb + OFF_WLO + ro);
            }
#pragma unroll
            for (int mf = 0; mf < 2; mf++)
#pragma unroll
                for (int nx = 0; nx < 2; nx++)
#pragma unroll
                    for (int sub = 0; sub < 2; sub++) {
                        int n8 = nx * 2 + sub;
                        mma_bf16(c[mf][n8], ah[mf], wh[nx][sub], wh[nx][sub + 2]);
                        mma_bf16(c[mf][n8], ah[mf], wl[nx][sub], wl[nx][sub + 2]);
                        mma_bf16(c[mf][n8], al[mf], wh[nx][sub], wh[nx][sub + 2]);
                    }
        }
    }

    // ---- stage C frags to SMEM ------------------------------------------------
    __syncthreads();
    float* outS = (float*)sm;
#pragma unroll
    for (int mf = 0; mf < 2; mf++)
#pragma unroll
        for (int n8 = 0; n8 < 4; n8++) {
            int rr = wm * 32 + mf * 16 + (lane >> 2);
            int cc = wn * 32 + n8 * 8 + (lane & 3) * 2;
            *(float2*)&outS[rr * OSTR + cc] =
                make_float2(c[mf][n8][0], c[mf][n8][1]);
            *(float2*)&outS[(rr + 8) * OSTR + cc] =
                make_float2(c[mf][n8][2], c[mf][n8][3]);
        }
    __syncthreads();

    // ---- bias + LayerNorm + ReLU; 4 threads per row ----------------------------
    {
        int r = tid >> 2;
        int q = tid & 3;
        float vals[32];
        float s = 0.f, ss = 0.f;
#pragma unroll
        for (int j = 0; j < 8; j++) {
            int col = q * 32 + j * 4;
            float4 y = *(const float4*)&outS[r * OSTR + col];
            float4 bb = __ldg((const float4*)&bias[col]);
            y.x += bb.x; y.y += bb.y; y.z += bb.z; y.w += bb.w;
            vals[4 * j + 0] = y.x; vals[4 * j + 1] = y.y;
            vals[4 * j + 2] = y.z; vals[4 * j + 3] = y.w;
            s += y.x + y.y + y.z + y.w;
            ss += y.x * y.x + y.y * y.y + y.z * y.z + y.w * y.w;
        }
        s  += __shfl_xor_sync(0xffffffffu, s, 1);
        s  += __shfl_xor_sync(0xffffffffu, s, 2);
        ss += __shfl_xor_sync(0xffffffffu, ss, 1);
        ss += __shfl_xor_sync(0xffffffffu, ss, 2);
        float mu = s * (1.0f / 128.0f);
        float var = ss * (1.0f / 128.0f) - mu * mu;
        float inv = rsqrtf(var + 1e-5f);

        int grow = row0 + r;
        if (grow < N_NODES) {
            float* gout = &out[(size_t)grow * 128];
#pragma unroll
            for (int j = 0; j < 8; j++) {
                int col = q * 32 + j * 4;
                float4 gm = __ldg((const float4*)&gamma[col]);
                float4 bt = __ldg((const float4*)&beta[col]);
                float4 o;
                o.x = (vals[4 * j + 0] - mu) * inv * gm.x + bt.x;
                o.y = (vals[4 * j + 1] - mu) * inv * gm.y + bt.y;
                o.z = (vals[4 * j + 2] - mu) * inv * gm.z + bt.z;
                o.w = (vals[4 * j + 3] - mu) * inv * gm.w + bt.w;
                o.x = o.x > 0.f ? o.x : 0.f;
                o.y = o.y > 0.f ? o.y : 0.f;
                o.z = o.z > 0.f ? o.z : 0.f;
                o.w = o.w > 0.f ? o.w : 0.f;
                *(float4*)&gout[col] = o;
            }
        }
    }
}

// ---------------- launcher ---------------------------------------------------
extern "C" void kernel_launch(void* const* d_in, const int* in_sizes, int n_in,
                              void* d_out, int out_size) {
    const float* h     = (const float*)d_in[0];
    const float* W     = (const float*)d_in[1];
    const float* b     = (const float*)d_in[2];
    const float* gamma = (const float*)d_in[3];
    const float* beta  = (const float*)d_in[4];
    const int*   src   = (const int*)d_in[5];
    const int*   dst   = (const int*)d_in[6];
    float* out = (float*)d_out;

    static int inited = 0;
    if (!inited) {
        cudaFuncSetAttribute(k_gemm_tc, cudaFuncAttributeMaxDynamicSharedMemorySize,
                             TC_SMEM);
        inited = 1;
    }

    k_init<<<(N_NODES + 255) / 256, 256>>>(W);
    k_count_convh<<<(N_NODES * 32 + 255) / 256, 256>>>(dst, h);
    k_scan1<<<SCAN_NBLK, 1024>>>();
    k_scan23<<<SCAN_NBLK, 1024>>>();
    k_scatter<<<(N_EDGES + 255) / 256, 256>>>(src, dst);
    k_aggregate<<<(N_NODES * 32 + 255) / 256, 256>>>(h);
    const int GBLK = (N_NODES + 127) / 128;   // 782
    k_gemm_tc<<<GBLK, 512, TC_SMEM>>>(b, gamma, beta, out);
}

// round 15
// speedup vs baseline: 1.0399x; 1.0399x over previous
#include <cuda_runtime.h>
#include <cuda_bf16.h>
#include <cstdint>

#define N_NODES 100000
#define N_EDGES 1600000
#define D 128
#define K2 256

#define SCAN_NBLK ((N_NODES + 4095) / 4096)   // 25

// ---------------- scratch (device globals; no allocation allowed) ----------
__device__ int   g_deg[N_NODES];
__device__ int   g_off[N_NODES + 1];
__device__ int   g_cursor[N_NODES];
__device__ int   g_srcs[N_EDGES];
__device__ int   g_blksum[32];
__device__ __nv_bfloat16 g_hhi[(size_t)N_NODES * D];    // h bf16 hi
__device__ __nv_bfloat16 g_hlo[(size_t)N_NODES * D];    // h bf16 lo
__device__ __nv_bfloat16 g_ahnhi[(size_t)N_NODES * D];  // ahn bf16 hi
__device__ __nv_bfloat16 g_ahnlo[(size_t)N_NODES * D];  // ahn bf16 lo
__device__ __nv_bfloat16 g_Whi[128 * 256];              // W bf16 hi
__device__ __nv_bfloat16 g_Wlo[128 * 256];              // W bf16 lo

__device__ __forceinline__ uint32_t pack_hi2(float a, float b, uint32_t& lo) {
    __nv_bfloat162 h2 = __floats2bfloat162_rn(a, b);
    float2 f = __bfloat1622float2(h2);
    __nv_bfloat162 l2 = __floats2bfloat162_rn(a - f.x, b - f.y);
    lo = *(uint32_t*)&l2;
    return *(uint32_t*)&h2;
}

// ---------------- init: zero degrees + convert W to bf16 hi/lo ---------------
__global__ void k_init(const float* __restrict__ W) {
    int i = blockIdx.x * blockDim.x + threadIdx.x;
    if (i < N_NODES) g_deg[i] = 0;
    if (i < 128 * 256) {
        float v = W[i];
        __nv_bfloat16 hi = __float2bfloat16(v);
        g_Whi[i] = hi;
        g_Wlo[i] = __float2bfloat16(v - __bfloat162float(hi));
    }
}

// ---- count degrees AND convert h -> bf16 hi/lo (disjoint thread ranges) -----
__global__ void k_count_convh(const int* __restrict__ dst,
                              const float* __restrict__ h) {
    int i = blockIdx.x * blockDim.x + threadIdx.x;   // 0 .. 3.2M-1
    if (i < N_EDGES) atomicAdd(&g_deg[dst[i]], 1);
    if (i < N_NODES * 32) {
        float4 v = ((const float4*)h)[i];
        uint32_t lo0, lo1;
        uint32_t hi0 = pack_hi2(v.x, v.y, lo0);
        uint32_t hi1 = pack_hi2(v.z, v.w, lo1);
        ((uint2*)g_hhi)[i] = make_uint2(hi0, hi1);
        ((uint2*)g_hlo)[i] = make_uint2(lo0, lo1);
    }
}

// ---- scan pass 1: per-block exclusive scan + block sums ---------------------
__global__ void k_scan1() {
    __shared__ int wsum[32];
    const int b = blockIdx.x, t = threadIdx.x;
    const int lane = t & 31, wid = t >> 5;
    const int base = b * 4096 + t * 4;

    int v0 = 0, v1 = 0, v2 = 0, v3 = 0;
    if (base + 3 < N_NODES) {
        int4 vv = *(const int4*)&g_deg[base];
        v0 = vv.x; v1 = vv.y; v2 = vv.z; v3 = vv.w;
    } else {
        if (base + 0 < N_NODES) v0 = g_deg[base + 0];
        if (base + 1 < N_NODES) v1 = g_deg[base + 1];
        if (base + 2 < N_NODES) v2 = g_deg[base + 2];
        if (base + 3 < N_NODES) v3 = g_deg[base + 3];
    }
    int tsum = v0 + v1 + v2 + v3;

    int x = tsum;
#pragma unroll
    for (int o = 1; o < 32; o <<= 1) {
        int y = __shfl_up_sync(0xffffffffu, x, o);
        if (lane >= o) x += y;
    }
    if (lane == 31) wsum[wid] = x;
    __syncthreads();
    if (wid == 0) {
        int w = wsum[lane];
        int xx = w;
#pragma unroll
        for (int o = 1; o < 32; o <<= 1) {
            int y = __shfl_up_sync(0xffffffffu, xx, o);
            if (lane >= o) xx += y;
        }
        wsum[lane] = xx - w;
        if (lane == 31) g_blksum[b] = xx;
    }
    __syncthreads();

    int prefix = wsum[wid] + (x - tsum);
    if (base + 3 < N_NODES) {
        *(int4*)&g_off[base] = make_int4(prefix, prefix + v0,
                                         prefix + v0 + v1, prefix + v0 + v1 + v2);
    } else {
        if (base + 0 < N_NODES) g_off[base + 0] = prefix;
        if (base + 1 < N_NODES) g_off[base + 1] = prefix + v0;
        if (base + 2 < N_NODES) g_off[base + 2] = prefix + v0 + v1;
        if (base + 3 < N_NODES) g_off[base + 3] = prefix + v0 + v1 + v2;
    }
}

// ---- scan pass 2: every block redundantly scans block sums, applies ---------
__global__ void k_scan23() {
    __shared__ int s_off;
    const int b = blockIdx.x, t = threadIdx.x;

    if (t < 32) {
        int v = (t < SCAN_NBLK) ? g_blksum[t] : 0;
        int x = v;
#pragma unroll
        for (int o = 1; o < 32; o <<= 1) {
            int y = __shfl_up_sync(0xffffffffu, x, o);
            if (t >= o) x += y;
        }
        if (t == b) s_off = x - v;
    }
    __syncthreads();
    const int off = s_off;

    const int base = b * 4096 + t * 4;
    if (base + 3 < N_NODES) {
        int4 vv = *(const int4*)&g_off[base];
        vv.x += off; vv.y += off; vv.z += off; vv.w += off;
        *(int4*)&g_off[base] = vv;
        *(int4*)&g_cursor[base] = vv;
    } else {
#pragma unroll
        for (int j = 0; j < 4; j++) {
            int idx = base + j;
            if (idx < N_NODES) {
                int val = g_off[idx] + off;
                g_off[idx] = val;
                g_cursor[idx] = val;
            }
        }
    }
    if (b == 0 && t == 0) g_off[N_NODES] = N_EDGES;
}

__global__ void k_scatter(const int* __restrict__ src, const int* __restrict__ dst) {
    int e = blockIdx.x * blockDim.x + threadIdx.x;
    if (e < N_EDGES) {
        int p = atomicAdd(&g_cursor[dst[e]], 1);
        g_srcs[p] = src[e];
    }
}

// ---------------- aggregation: fp32 gather, write bf16 hi/lo -----------------
__global__ void k_aggregate(const float* __restrict__ h) {
    int warp = (blockIdx.x * blockDim.x + threadIdx.x) >> 5;
    int lane = threadIdx.x & 31;
    if (warp >= N_NODES) return;
    int beg = g_off[warp];
    int end = g_off[warp + 1];
    const float4* h4 = (const float4*)h;
    float4 acc0 = make_float4(0.f, 0.f, 0.f, 0.f);
    float4 acc1 = make_float4(0.f, 0.f, 0.f, 0.f);
    int e = beg;
    for (; e + 3 < end; e += 4) {
        int s0 = __ldg(&g_srcs[e]);
        int s1 = __ldg(&g_srcs[e + 1]);
        int s2 = __ldg(&g_srcs[e + 2]);
        int s3 = __ldg(&g_srcs[e + 3]);
        float4 v0 = __ldg(&h4[(size_t)s0 * 32 + lane]);
        float4 v1 = __ldg(&h4[(size_t)s1 * 32 + lane]);
        float4 v2 = __ldg(&h4[(size_t)s2 * 32 + lane]);
        float4 v3 = __ldg(&h4[(size_t)s3 * 32 + lane]);
        acc0.x += v0.x; acc0.y += v0.y; acc0.z += v0.z; acc0.w += v0.w;
        acc1.x += v1.x; acc1.y += v1.y; acc1.z += v1.z; acc1.w += v1.w;
        acc0.x += v2.x; acc0.y += v2.y; acc0.z += v2.z; acc0.w += v2.w;
        acc1.x += v3.x; acc1.y += v3.y; acc1.z += v3.z; acc1.w += v3.w;
    }
    for (; e < end; e++) {
        int s0 = __ldg(&g_srcs[e]);
        float4 v0 = __ldg(&h4[(size_t)s0 * 32 + lane]);
        acc0.x += v0.x; acc0.y += v0.y; acc0.z += v0.z; acc0.w += v0.w;
    }
    acc0.x += acc1.x; acc0.y += acc1.y; acc0.z += acc1.z; acc0.w += acc1.w;
    float norm = (end > beg) ? 1.0f / (float)(end - beg) : 0.0f;
    acc0.x *= norm; acc0.y *= norm; acc0.z *= norm; acc0.w *= norm;

    uint32_t lo0, lo1;
    uint32_t hi0 = pack_hi2(acc0.x, acc0.y, lo0);
    uint32_t hi1 = pack_hi2(acc0.z, acc0.w, lo1);
    ((uint2*)g_ahnhi)[(size_t)warp * 32 + lane] = make_uint2(hi0, hi1);
    ((uint2*)g_ahnlo)[(size_t)warp * 32 + lane] = make_uint2(lo0, lo1);
}

// =============== tensor-core GEMM + LN + ReLU (mma.sync bf16 hi/lo) ==========
// CTA: 128x128, 512 threads. K=256 in 4 chunks of 64, DOUBLE-BUFFERED with
// register prefetch of pre-converted bf16 hi/lo operands (zero cvt in loop).
#define ASTR 72
#define ABYTES (128 * ASTR * 2)
#define BUFBYTES (4 * ABYTES)
#define OFF_AHI 0
#define OFF_ALO (ABYTES)
#define OFF_WHI (2 * ABYTES)
#define OFF_WLO (3 * ABYTES)
#define TC_SMEM (2 * BUFBYTES)         // 147456
#define OSTR 132

__device__ __forceinline__ uint32_t smem_u32(const void* p) {
    uint32_t a;
    asm("{ .reg .u64 t; cvta.to.shared.u64 t, %1; cvt.u32.u64 %0, t; }"
        : "=r"(a) : "l"(p));
    return a;
}

__device__ __forceinline__ void ldm4(uint32_t* r, uint32_t addr) {
    asm volatile("ldmatrix.sync.aligned.m8n8.x4.shared.b16 {%0,%1,%2,%3}, [%4];"
        : "=r"(r[0]), "=r"(r[1]), "=r"(r[2]), "=r"(r[3]) : "r"(addr));
}

__device__ __forceinline__ void mma_bf16(float* c, const uint32_t* a,
                                         uint32_t b0, uint32_t b1) {
    asm volatile("mma.sync.aligned.m16n8k16.row.col.f32.bf16.bf16.f32 "
        "{%0,%1,%2,%3}, {%4,%5,%6,%7}, {%8,%9}, {%0,%1,%2,%3};"
        : "+f"(c[0]), "+f"(c[1]), "+f"(c[2]), "+f"(c[3])
        : "r"(a[0]), "r"(a[1]), "r"(a[2]), "r"(a[3]), "r"(b0), "r"(b1));
}

__global__ void __launch_bounds__(512, 1)
k_gemm_tc(const float* __restrict__ bias,
          const float* __restrict__ gamma,
          const float* __restrict__ beta,
          float* __restrict__ out)
{
    extern __shared__ char sm[];
    const uint32_t smb = smem_u32(sm);

    const int tid = threadIdx.x;
    const int wid = tid >> 5;
    const int lane = tid & 31;
    const int wm = wid & 3;
    const int wn = wid >> 2;
    const int row0 = blockIdx.x * 128;

    const int sr = tid >> 2;       // staging row 0..127
    const int sq = tid & 3;        // staging quarter (16 bf16 = 32 B)

    float c[2][4][4];
#pragma unroll
    for (int i = 0; i < 2; i++)
#pragma unroll
        for (int j = 0; j < 4; j++)
#pragma unroll
            for (int k = 0; k < 4; k++) c[i][j][k] = 0.f;

    const int lrow = lane & 15;
    const int lhalfB = (lane >> 4) * 16;
    const uint32_t aRowB = (uint32_t)(wm * 32 + lrow) * (ASTR * 2);
    const uint32_t wRowB = (uint32_t)(wn * 32 + lrow) * (ASTR * 2);

    int growA = row0 + sr;
    if (growA >= N_NODES) growA = N_NODES - 1;
    const size_t aRow = (size_t)growA * 128;   // bf16 elems per A row
    const int wRow = sr * 256;                 // bf16 elems per W row
    const uint32_t stByteOff = (uint32_t)((sr * ASTR + sq * 16) * 2);

    // ---- stage chunk 0 into buffer 0 ----------------------------------------
    {
        const int acol = sq * 16;
        const int wcol = sq * 16;
        uint4 a0 = __ldg((const uint4*)(g_hhi + aRow + acol));
        uint4 a1 = __ldg((const uint4*)(g_hhi + aRow + acol + 8));
        uint4 l0 = __ldg((const uint4*)(g_hlo + aRow + acol));
        uint4 l1 = __ldg((const uint4*)(g_hlo + aRow + acol + 8));
        uint4 w0 = __ldg((const uint4*)(g_Whi + wRow + wcol));
        uint4 w1 = __ldg((const uint4*)(g_Whi + wRow + wcol + 8));
        uint4 x0 = __ldg((const uint4*)(g_Wlo + wRow + wcol));
        uint4 x1 = __ldg((const uint4*)(g_Wlo + wRow + wcol + 8));
        char* p;
        p = sm + OFF_AHI + stByteOff; *(uint4*)p = a0; *(uint4*)(p + 16) = a1;
        p = sm + OFF_ALO + stByteOff; *(uint4*)p = l0; *(uint4*)(p + 16) = l1;
        p = sm + OFF_WHI + stByteOff; *(uint4*)p = w0; *(uint4*)(p + 16) = w1;
        p = sm + OFF_WLO + stByteOff; *(uint4*)p = x0; *(uint4*)(p + 16) = x1;
    }
    __syncthreads();

#pragma unroll
    for (int kb = 0; kb < 4; kb++) {
        const bool more = kb < 3;
        uint4 pre[8];
        if (more) {
            int kn = kb + 1;
            const __nv_bfloat16* ahis = (kn < 2) ? g_hhi : g_ahnhi;
            const __nv_bfloat16* alos = (kn < 2) ? g_hlo : g_ahnlo;
            const int acol = (kn & 1) * 64 + sq * 16;
            const int wcol = kn * 64 + sq * 16;
            pre[0] = __ldg((const uint4*)(ahis + aRow + acol));
            pre[1] = __ldg((const uint4*)(ahis + aRow + acol + 8));
            pre[2] = __ldg((const uint4*)(alos + aRow + acol));
            pre[3] = __ldg((const uint4*)(alos + aRow + acol + 8));
            pre[4] = __ldg((const uint4*)(g_Whi + wRow + wcol));
            pre[5] = __ldg((const uint4*)(g_Whi + wRow + wcol + 8));
            pre[6] = __ldg((const uint4*)(g_Wlo + wRow + wcol));
            pre[7] = __ldg((const uint4*)(g_Wlo + wRow + wcol + 8));
        }

        const uint32_t bufB = (uint32_t)((kb & 1) * BUFBYTES);
        // ---- mma over current chunk: 4 k-steps of 16 ------------------------
#pragma unroll
        for (int ks = 0; ks < 4; ks++) {
            const uint32_t cb = (uint32_t)(ks * 32 + lhalfB);
            uint32_t ah[2][4], al[2][4], wh[2][4], wl[2][4];
#pragma unroll
            for (int mf = 0; mf < 2; mf++) {
                uint32_t ro = aRowB + mf * 16 * (ASTR * 2) + cb;
                ldm4(ah[mf], smb + bufB + OFF_AHI + ro);
                ldm4(al[mf], smb + bufB + OFF_ALO + ro);
            }
#pragma unroll
            for (int nx = 0; nx < 2; nx++) {
                uint32_t ro = wRowB + nx * 16 * (ASTR * 2) + cb;
                ldm4(wh[nx], smb + bufB + OFF_WHI + ro);
                ldm4(wl[nx], smb + bufB + OFF_WLO + ro);
            }
#pragma unroll
            for (int mf = 0; mf < 2; mf++)
#pragma unroll
                for (int nx = 0; nx < 2; nx++)
#pragma unroll
                    for (int sub = 0; sub < 2; sub++) {
                        int n8 = nx * 2 + sub;
                        mma_bf16(c[mf][n8], ah[mf], wh[nx][sub], wh[nx][sub + 2]);
                        mma_bf16(c[mf][n8], ah[mf], wl[nx][sub], wl[nx][sub + 2]);
                        mma_bf16(c[mf][n8], al[mf], wh[nx][sub], wh[nx][sub + 2]);
                    }
        }

        if (more) {
            const uint32_t nbB = (uint32_t)(((kb + 1) & 1) * BUFBYTES);
            char* p;
            p = sm + nbB + OFF_AHI + stByteOff;
            *(uint4*)p = pre[0]; *(uint4*)(p + 16) = pre[1];
            p = sm + nbB + OFF_ALO + stByteOff;
            *(uint4*)p = pre[2]; *(uint4*)(p + 16) = pre[3];
            p = sm + nbB + OFF_WHI + stByteOff;
            *(uint4*)p = pre[4]; *(uint4*)(p + 16) = pre[5];
            p = sm + nbB + OFF_WLO + stByteOff;
            *(uint4*)p = pre[6]; *(uint4*)(p + 16) = pre[7];
            __syncthreads();
        }
    }

    // ---- stage C frags to SMEM ------------------------------------------------
    __syncthreads();
    float* outS = (float*)sm;
#pragma unroll
    for (int mf = 0; mf < 2; mf++)
#pragma unroll
        for (int n8 = 0; n8 < 4; n8++) {
            int rr = wm * 32 + mf * 16 + (lane >> 2);
            int cc = wn * 32 + n8 * 8 + (lane & 3) * 2;
            *(float2*)&outS[rr * OSTR + cc] =
                make_float2(c[mf][n8][0], c[mf][n8][1]);
            *(float2*)&outS[(rr + 8) * OSTR + cc] =
                make_float2(c[mf][n8][2], c[mf][n8][3]);
        }
    __syncthreads();

    // ---- bias + LayerNorm + ReLU; 4 threads per row ----------------------------
    {
        int r = tid >> 2;
        int q = tid & 3;
        float vals[32];
        float s = 0.f, ss = 0.f;
#pragma unroll
        for (int j = 0; j < 8; j++) {
            int col = q * 32 + j * 4;
            float4 y = *(const float4*)&outS[r * OSTR + col];
            float4 bb = __ldg((const float4*)&bias[col]);
            y.x += bb.x; y.y += bb.y; y.z += bb.z; y.w += bb.w;
            vals[4 * j + 0] = y.x; vals[4 * j + 1] = y.y;
            vals[4 * j + 2] = y.z; vals[4 * j + 3] = y.w;
            s += y.x + y.y + y.z + y.w;
            ss += y.x * y.x + y.y * y.y + y.z * y.z + y.w * y.w;
        }
        s  += __shfl_xor_sync(0xffffffffu, s, 1);
        s  += __shfl_xor_sync(0xffffffffu, s, 2);
        ss += __shfl_xor_sync(0xffffffffu, ss, 1);
        ss += __shfl_xor_sync(0xffffffffu, ss, 2);
        float mu = s * (1.0f / 128.0f);
        float var = ss * (1.0f / 128.0f) - mu * mu;
        float inv = rsqrtf(var + 1e-5f);

        int grow = row0 + r;
        if (grow < N_NODES) {
            float* gout = &out[(size_t)grow * 128];
#pragma unroll
            for (int j = 0; j < 8; j++) {
                int col = q * 32 + j * 4;
                float4 gm = __ldg((const float4*)&gamma[col]);
                float4 bt = __ldg((const float4*)&beta[col]);
                float4 o;
                o.x = (vals[4 * j + 0] - mu) * inv * gm.x + bt.x;
                o.y = (vals[4 * j + 1] - mu) * inv * gm.y + bt.y;
                o.z = (vals[4 * j + 2] - mu) * inv * gm.z + bt.z;
                o.w = (vals[4 * j + 3] - mu) * inv * gm.w + bt.w;
                o.x = o.x > 0.f ? o.x : 0.f;
                o.y = o.y > 0.f ? o.y : 0.f;
                o.z = o.z > 0.f ? o.z : 0.f;
                o.w = o.w > 0.f ? o.w : 0.f;
                *(float4*)&gout[col] = o;
            }
        }
    }
}

// ---------------- launcher ---------------------------------------------------
extern "C" void kernel_launch(void* const* d_in, const int* in_sizes, int n_in,
                              void* d_out, int out_size) {
    const float* h     = (const float*)d_in[0];
    const float* W     = (const float*)d_in[1];
    const float* b     = (const float*)d_in[2];
    const float* gamma = (const float*)d_in[3];
    const float* beta  = (const float*)d_in[4];
    const int*   src   = (const int*)d_in[5];
    const int*   dst   = (const int*)d_in[6];
    float* out = (float*)d_out;

    static int inited = 0;
    if (!inited) {
        cudaFuncSetAttribute(k_gemm_tc, cudaFuncAttributeMaxDynamicSharedMemorySize,
                             TC_SMEM);
        inited = 1;
    }

    k_init<<<(N_NODES + 255) / 256, 256>>>(W);
    k_count_convh<<<(N_NODES * 32 + 255) / 256, 256>>>(dst, h);
    k_scan1<<<SCAN_NBLK, 1024>>>();
    k_scan23<<<SCAN_NBLK, 1024>>>();
    k_scatter<<<(N_EDGES + 255) / 256, 256>>>(src, dst);
    k_aggregate<<<(N_NODES * 32 + 255) / 256, 256>>>(h);
    const int GBLK = (N_NODES + 127) / 128;   // 782
    k_gemm_tc<<<GBLK, 512, TC_SMEM>>>(b, gamma, beta, out);
}

// round 16
// speedup vs baseline: 1.2753x; 1.2264x over previous
#include <cuda_runtime.h>
#include <cuda_fp16.h>
#include <cstdint>

#define N_NODES 100000
#define N_EDGES 1600000
#define D 128
#define K2 256

#define SCAN_NBLK ((N_NODES + 4095) / 4096)   // 25

// ---------------- scratch (device globals; no allocation allowed) ----------
__device__ int   g_deg[N_NODES];
__device__ int   g_off[N_NODES + 1];
__device__ int   g_cursor[N_NODES];
__device__ int   g_srcs[N_EDGES];
__device__ int   g_blksum[32];
__device__ __half g_h16[(size_t)N_NODES * D];     // h fp16
__device__ __half g_ahn16[(size_t)N_NODES * D];   // ahn fp16
__device__ __half g_W16[128 * 256];               // W fp16

// ---------------- init: zero degrees + convert W -> fp16 ---------------------
__global__ void k_init(const float* __restrict__ W) {
    int i = blockIdx.x * blockDim.x + threadIdx.x;
    if (i < N_NODES) g_deg[i] = 0;
    if (i < 128 * 256) g_W16[i] = __float2half_rn(W[i]);
}

// ---- count degrees AND convert h -> fp16 (disjoint thread ranges) -----------
__global__ void k_count_convh(const int* __restrict__ dst,
                              const float* __restrict__ h) {
    int i = blockIdx.x * blockDim.x + threadIdx.x;   // 0 .. 3.2M-1
    if (i < N_EDGES) atomicAdd(&g_deg[dst[i]], 1);
    if (i < N_NODES * 32) {
        float4 v = ((const float4*)h)[i];
        __half2 p0 = __floats2half2_rn(v.x, v.y);
        __half2 p1 = __floats2half2_rn(v.z, v.w);
        ((uint2*)g_h16)[i] = make_uint2(*(uint32_t*)&p0, *(uint32_t*)&p1);
    }
}

// ---- scan pass 1: per-block exclusive scan + block sums ---------------------
__global__ void k_scan1() {
    __shared__ int wsum[32];
    const int b = blockIdx.x, t = threadIdx.x;
    const int lane = t & 31, wid = t >> 5;
    const int base = b * 4096 + t * 4;

    int v0 = 0, v1 = 0, v2 = 0, v3 = 0;
    if (base + 3 < N_NODES) {
        int4 vv = *(const int4*)&g_deg[base];
        v0 = vv.x; v1 = vv.y; v2 = vv.z; v3 = vv.w;
    } else {
        if (base + 0 < N_NODES) v0 = g_deg[base + 0];
        if (base + 1 < N_NODES) v1 = g_deg[base + 1];
        if (base + 2 < N_NODES) v2 = g_deg[base + 2];
        if (base + 3 < N_NODES) v3 = g_deg[base + 3];
    }
    int tsum = v0 + v1 + v2 + v3;

    int x = tsum;
#pragma unroll
    for (int o = 1; o < 32; o <<= 1) {
        int y = __shfl_up_sync(0xffffffffu, x, o);
        if (lane >= o) x += y;
    }
    if (lane == 31) wsum[wid] = x;
    __syncthreads();
    if (wid == 0) {
        int w = wsum[lane];
        int xx = w;
#pragma unroll
        for (int o = 1; o < 32; o <<= 1) {
            int y = __shfl_up_sync(0xffffffffu, xx, o);
            if (lane >= o) xx += y;
        }
        wsum[lane] = xx - w;
        if (lane == 31) g_blksum[b] = xx;
    }
    __syncthreads();

    int prefix = wsum[wid] + (x - tsum);
    if (base + 3 < N_NODES) {
        *(int4*)&g_off[base] = make_int4(prefix, prefix + v0,
                                         prefix + v0 + v1, prefix + v0 + v1 + v2);
    } else {
        if (base + 0 < N_NODES) g_off[base + 0] = prefix;
        if (base + 1 < N_NODES) g_off[base + 1] = prefix + v0;
        if (base + 2 < N_NODES) g_off[base + 2] = prefix + v0 + v1;
        if (base + 3 < N_NODES) g_off[base + 3] = prefix + v0 + v1 + v2;
    }
}

// ---- scan pass 2: every block redundantly scans block sums, applies ---------
__global__ void k_scan23() {
    __shared__ int s_off;
    const int b = blockIdx.x, t = threadIdx.x;

    if (t < 32) {
        int v = (t < SCAN_NBLK) ? g_blksum[t] : 0;
        int x = v;
#pragma unroll
        for (int o = 1; o < 32; o <<= 1) {
            int y = __shfl_up_sync(0xffffffffu, x, o);
            if (t >= o) x += y;
        }
        if (t == b) s_off = x - v;
    }
    __syncthreads();
    const int off = s_off;

    const int base = b * 4096 + t * 4;
    if (base + 3 < N_NODES) {
        int4 vv = *(const int4*)&g_off[base];
        vv.x += off; vv.y += off; vv.z += off; vv.w += off;
        *(int4*)&g_off[base] = vv;
        *(int4*)&g_cursor[base] = vv;
    } else {
#pragma unroll
        for (int j = 0; j < 4; j++) {
            int idx = base + j;
            if (idx < N_NODES) {
                int val = g_off[idx] + off;
                g_off[idx] = val;
                g_cursor[idx] = val;
            }
        }
    }
    if (b == 0 && t == 0) g_off[N_NODES] = N_EDGES;
}

__global__ void k_scatter(const int* __restrict__ src, const int* __restrict__ dst) {
    int e = blockIdx.x * blockDim.x + threadIdx.x;
    if (e < N_EDGES) {
        int p = atomicAdd(&g_cursor[dst[e]], 1);
        g_srcs[p] = src[e];
    }
}

// ---------------- aggregation: fp32 gather, write fp16 -----------------------
__global__ void k_aggregate(const float* __restrict__ h) {
    int warp = (blockIdx.x * blockDim.x + threadIdx.x) >> 5;
    int lane = threadIdx.x & 31;
    if (warp >= N_NODES) return;
    int beg = g_off[warp];
    int end = g_off[warp + 1];
    const float4* h4 = (const float4*)h;
    float4 acc0 = make_float4(0.f, 0.f, 0.f, 0.f);
    float4 acc1 = make_float4(0.f, 0.f, 0.f, 0.f);
    int e = beg;
    for (; e + 3 < end; e += 4) {
        int s0 = __ldg(&g_srcs[e]);
        int s1 = __ldg(&g_srcs[e + 1]);
        int s2 = __ldg(&g_srcs[e + 2]);
        int s3 = __ldg(&g_srcs[e + 3]);
        float4 v0 = __ldg(&h4[(size_t)s0 * 32 + lane]);
        float4 v1 = __ldg(&h4[(size_t)s1 * 32 + lane]);
        float4 v2 = __ldg(&h4[(size_t)s2 * 32 + lane]);
        float4 v3 = __ldg(&h4[(size_t)s3 * 32 + lane]);
        acc0.x += v0.x; acc0.y += v0.y; acc0.z += v0.z; acc0.w += v0.w;
        acc1.x += v1.x; acc1.y += v1.y; acc1.z += v1.z; acc1.w += v1.w;
        acc0.x += v2.x; acc0.y += v2.y; acc0.z += v2.z; acc0.w += v2.w;
        acc1.x += v3.x; acc1.y += v3.y; acc1.z += v3.z; acc1.w += v3.w;
    }
    for (; e < end; e++) {
        int s0 = __ldg(&g_srcs[e]);
        float4 v0 = __ldg(&h4[(size_t)s0 * 32 + lane]);
        acc0.x += v0.x; acc0.y += v0.y; acc0.z += v0.z; acc0.w += v0.w;
    }
    acc0.x += acc1.x; acc0.y += acc1.y; acc0.z += acc1.z; acc0.w += acc1.w;
    float norm = (end > beg) ? 1.0f / (float)(end - beg) : 0.0f;
    acc0.x *= norm; acc0.y *= norm; acc0.z *= norm; acc0.w *= norm;

    __half2 p0 = __floats2half2_rn(acc0.x, acc0.y);
    __half2 p1 = __floats2half2_rn(acc0.z, acc0.w);
    ((uint2*)g_ahn16)[(size_t)warp * 32 + lane] =
        make_uint2(*(uint32_t*)&p0, *(uint32_t*)&p1);
}

// =============== tensor-core GEMM + LN + ReLU (mma.sync fp16, 1 term) ========
// CTA: 128x128, 512 threads. K=256 in 4 chunks of 64, DOUBLE-BUFFERED with
// register prefetch. Single fp16 term (fp32 accumulate).
#define ASTR 72
#define ABYTES (128 * ASTR * 2)
#define BUFBYTES (2 * ABYTES)          // A | W
#define OFF_A 0
#define OFF_W (ABYTES)
#define TC_SMEM (2 * BUFBYTES)         // 73728
#define OSTR 132

__device__ __forceinline__ uint32_t smem_u32(const void* p) {
    uint32_t a;
    asm("{ .reg .u64 t; cvta.to.shared.u64 t, %1; cvt.u32.u64 %0, t; }"
        : "=r"(a) : "l"(p));
    return a;
}

__device__ __forceinline__ void ldm4(uint32_t* r, uint32_t addr) {
    asm volatile("ldmatrix.sync.aligned.m8n8.x4.shared.b16 {%0,%1,%2,%3}, [%4];"
        : "=r"(r[0]), "=r"(r[1]), "=r"(r[2]), "=r"(r[3]) : "r"(addr));
}

__device__ __forceinline__ void mma_f16(float* c, const uint32_t* a,
                                        uint32_t b0, uint32_t b1) {
    asm volatile("mma.sync.aligned.m16n8k16.row.col.f32.f16.f16.f32 "
        "{%0,%1,%2,%3}, {%4,%5,%6,%7}, {%8,%9}, {%0,%1,%2,%3};"
        : "+f"(c[0]), "+f"(c[1]), "+f"(c[2]), "+f"(c[3])
        : "r"(a[0]), "r"(a[1]), "r"(a[2]), "r"(a[3]), "r"(b0), "r"(b1));
}

__global__ void __launch_bounds__(512, 1)
k_gemm_tc(const float* __restrict__ bias,
          const float* __restrict__ gamma,
          const float* __restrict__ beta,
          float* __restrict__ out)
{
    extern __shared__ char sm[];
    const uint32_t smb = smem_u32(sm);

    const int tid = threadIdx.x;
    const int wid = tid >> 5;
    const int lane = tid & 31;
    const int wm = wid & 3;
    const int wn = wid >> 2;
    const int row0 = blockIdx.x * 128;

    const int sr = tid >> 2;       // staging row 0..127
    const int sq = tid & 3;        // staging quarter (16 fp16 = 32 B)

    float c[2][4][4];
#pragma unroll
    for (int i = 0; i < 2; i++)
#pragma unroll
        for (int j = 0; j < 4; j++)
#pragma unroll
            for (int k = 0; k < 4; k++) c[i][j][k] = 0.f;

    const int lrow = lane & 15;
    const int lhalfB = (lane >> 4) * 16;
    const uint32_t aRowB = (uint32_t)(wm * 32 + lrow) * (ASTR * 2);
    const uint32_t wRowB = (uint32_t)(wn * 32 + lrow) * (ASTR * 2);

    int growA = row0 + sr;
    if (growA >= N_NODES) growA = N_NODES - 1;
    const size_t aRow = (size_t)growA * 128;   // fp16 elems per A row
    const int wRow = sr * 256;                 // fp16 elems per W row
    const uint32_t stByteOff = (uint32_t)((sr * ASTR + sq * 16) * 2);

    // ---- stage chunk 0 into buffer 0 ----------------------------------------
    {
        uint4 a0 = __ldg((const uint4*)(g_h16 + aRow + sq * 16));
        uint4 a1 = __ldg((const uint4*)(g_h16 + aRow + sq * 16 + 8));
        uint4 w0 = __ldg((const uint4*)(g_W16 + wRow + sq * 16));
        uint4 w1 = __ldg((const uint4*)(g_W16 + wRow + sq * 16 + 8));
        char* p;
        p = sm + OFF_A + stByteOff; *(uint4*)p = a0; *(uint4*)(p + 16) = a1;
        p = sm + OFF_W + stByteOff; *(uint4*)p = w0; *(uint4*)(p + 16) = w1;
    }
    __syncthreads();

#pragma unroll
    for (int kb = 0; kb < 4; kb++) {
        const bool more = kb < 3;
        uint4 pre[4];
        if (more) {
            int kn = kb + 1;
            const __half* asrc = (kn < 2) ? g_h16 : g_ahn16;
            const int acol = (kn & 1) * 64 + sq * 16;
            const int wcol = kn * 64 + sq * 16;
            pre[0] = __ldg((const uint4*)(asrc + aRow + acol));
            pre[1] = __ldg((const uint4*)(asrc + aRow + acol + 8));
            pre[2] = __ldg((const uint4*)(g_W16 + wRow + wcol));
            pre[3] = __ldg((const uint4*)(g_W16 + wRow + wcol + 8));
        }

        const uint32_t bufB = (uint32_t)((kb & 1) * BUFBYTES);
        // ---- mma over current chunk: 4 k-steps of 16 ------------------------
#pragma unroll
        for (int ks = 0; ks < 4; ks++) {
            const uint32_t cb = (uint32_t)(ks * 32 + lhalfB);
            uint32_t af[2][4], wf[2][4];
#pragma unroll
            for (int mf = 0; mf < 2; mf++)
                ldm4(af[mf], smb + bufB + OFF_A + aRowB + mf * 16 * (ASTR * 2) + cb);
#pragma unroll
            for (int nx = 0; nx < 2; nx++)
                ldm4(wf[nx], smb + bufB + OFF_W + wRowB + nx * 16 * (ASTR * 2) + cb);
#pragma unroll
            for (int mf = 0; mf < 2; mf++)
#pragma unroll
                for (int nx = 0; nx < 2; nx++)
#pragma unroll
                    for (int sub = 0; sub < 2; sub++)
                        mma_f16(c[mf][nx * 2 + sub], af[mf],
                                wf[nx][sub], wf[nx][sub + 2]);
        }

        if (more) {
            const uint32_t nbB = (uint32_t)(((kb + 1) & 1) * BUFBYTES);
            char* p;
            p = sm + nbB + OFF_A + stByteOff;
            *(uint4*)p = pre[0]; *(uint4*)(p + 16) = pre[1];
            p = sm + nbB + OFF_W + stByteOff;
            *(uint4*)p = pre[2]; *(uint4*)(p + 16) = pre[3];
            __syncthreads();
        }
    }

    // ---- stage C frags to SMEM ------------------------------------------------
    __syncthreads();
    float* outS = (float*)sm;
#pragma unroll
    for (int mf = 0; mf < 2; mf++)
#pragma unroll
        for (int n8 = 0; n8 < 4; n8++) {
            int rr = wm * 32 + mf * 16 + (lane >> 2);
            int cc = wn * 32 + n8 * 8 + (lane & 3) * 2;
            *(float2*)&outS[rr * OSTR + cc] =
                make_float2(c[mf][n8][0], c[mf][n8][1]);
            *(float2*)&outS[(rr + 8) * OSTR + cc] =
                make_float2(c[mf][n8][2], c[mf][n8][3]);
        }
    __syncthreads();

    // ---- bias + LayerNorm + ReLU; 4 threads per row ----------------------------
    {
        int r = tid >> 2;
        int q = tid & 3;
        float vals[32];
        float s = 0.f, ss = 0.f;
#pragma unroll
        for (int j = 0; j < 8; j++) {
            int col = q * 32 + j * 4;
            float4 y = *(const float4*)&outS[r * OSTR + col];
            float4 bb = __ldg((const float4*)&bias[col]);
            y.x += bb.x; y.y += bb.y; y.z += bb.z; y.w += bb.w;
            vals[4 * j + 0] = y.x; vals[4 * j + 1] = y.y;
            vals[4 * j + 2] = y.z; vals[4 * j + 3] = y.w;
            s += y.x + y.y + y.z + y.w;
            ss += y.x * y.x + y.y * y.y + y.z * y.z + y.w * y.w;
        }
        s  += __shfl_xor_sync(0xffffffffu, s, 1);
        s  += __shfl_xor_sync(0xffffffffu, s, 2);
        ss += __shfl_xor_sync(0xffffffffu, ss, 1);
        ss += __shfl_xor_sync(0xffffffffu, ss, 2);
        float mu = s * (1.0f / 128.0f);
        float var = ss * (1.0f / 128.0f) - mu * mu;
        float inv = rsqrtf(var + 1e-5f);

        int grow = row0 + r;
        if (grow < N_NODES) {
            float* gout = &out[(size_t)grow * 128];
#pragma unroll
            for (int j = 0; j < 8; j++) {
                int col = q * 32 + j * 4;
                float4 gm = __ldg((const float4*)&gamma[col]);
                float4 bt = __ldg((const float4*)&beta[col]);
                float4 o;
                o.x = (vals[4 * j + 0] - mu) * inv * gm.x + bt.x;
                o.y = (vals[4 * j + 1] - mu) * inv * gm.y + bt.y;
                o.z = (vals[4 * j + 2] - mu) * inv * gm.z + bt.z;
                o.w = (vals[4 * j + 3] - mu) * inv * gm.w + bt.w;
                o.x = o.x > 0.f ? o.x : 0.f;
                o.y = o.y > 0.f ? o.y : 0.f;
                o.z = o.z > 0.f ? o.z : 0.f;
                o.w = o.w > 0.f ? o.w : 0.f;
                *(float4*)&gout[col] = o;
            }
        }
    }
}

// ---------------- launcher ---------------------------------------------------
extern "C" void kernel_launch(void* const* d_in, const int* in_sizes, int n_in,
                              void* d_out, int out_size) {
    const float* h     = (const float*)d_in[0];
    const float* W     = (const float*)d_in[1];
    const float* b     = (const float*)d_in[2];
    const float* gamma = (const float*)d_in[3];
    const float* beta  = (const float*)d_in[4];
    const int*   src   = (const int*)d_in[5];
    const int*   dst   = (const int*)d_in[6];
    float* out = (float*)d_out;

    static int inited = 0;
    if (!inited) {
        cudaFuncSetAttribute(k_gemm_tc, cudaFuncAttributeMaxDynamicSharedMemorySize,
                             TC_SMEM);
        inited = 1;
    }

    k_init<<<(N_NODES + 255) / 256, 256>>>(W);
    k_count_convh<<<(N_NODES * 32 + 255) / 256, 256>>>(dst, h);
    k_scan1<<<SCAN_NBLK, 1024>>>();
    k_scan23<<<SCAN_NBLK, 1024>>>();
    k_scatter<<<(N_EDGES + 255) / 256, 256>>>(src, dst);
    k_aggregate<<<(N_NODES * 32 + 255) / 256, 256>>>(h);
    const int GBLK = (N_NODES + 127) / 128;   // 782
    k_gemm_tc<<<GBLK, 512, TC_SMEM>>>(b, gamma, beta, out);
}